// round 8
// baseline (speedup 1.0000x reference)
#include <cuda_runtime.h>
#include <cuda_bf16.h>
#include <cuda_fp16.h>
#include <math.h>
#include <stdint.h>

constexpr int Bsz = 8, Ssz = 1024, Dsz = 1024, Hsz = 16, DKsz = 64, FFsz = 4096;
constexpr int MR = Bsz * Ssz;          // 8192
constexpr int NQ = 3 * Hsz * DKsz;     // 3072

typedef __nv_bfloat16 bf16;

// ---------------------------------------------------------------------------
// Static device scratch (no allocations allowed)
// ---------------------------------------------------------------------------
__device__ int    g_mask_mode;
__device__ bf16   g_Xh[(size_t)MR * Dsz],      g_Xl[(size_t)MR * Dsz];
__device__ bf16   g_Wqkvh[(size_t)NQ * Dsz],   g_Wqkvl[(size_t)NQ * Dsz];
__device__ bf16   g_FCh[(size_t)Dsz * Dsz],    g_FCl[(size_t)Dsz * Dsz];
__device__ bf16   g_W1h[(size_t)FFsz * Dsz],   g_W1l[(size_t)FFsz * Dsz];
__device__ bf16   g_W2h[(size_t)Dsz * FFsz],   g_W2l[(size_t)Dsz * FFsz];
__device__ bf16   g_QKVh[(size_t)MR * NQ],     g_QKVl[(size_t)MR * NQ];
__device__ bf16   g_Vth[(size_t)Bsz * Hsz * DKsz * Ssz], g_Vtl[(size_t)Bsz * Hsz * DKsz * Ssz];
__device__ __half g_Sh[(size_t)Bsz * Hsz * Ssz * Ssz];       // fp16 masked/scaled logits
__device__ float  g_CM[(size_t)Bsz * Hsz * Ssz];             // per-(b,h,k) column max
__device__ float  g_CI[(size_t)Bsz * Hsz * Ssz];             // per-(b,h,k) 1/sum(exp)
__device__ bf16   g_Oh[(size_t)MR * Dsz],      g_Ol[(size_t)MR * Dsz];
__device__ float  g_ATT[(size_t)MR * Dsz];
__device__ float  g_X1[(size_t)MR * Dsz];
__device__ bf16   g_X1h[(size_t)MR * Dsz],     g_X1l[(size_t)MR * Dsz];
__device__ bf16   g_H1h[(size_t)MR * FFsz],    g_H1l[(size_t)MR * FFsz];
__device__ float  g_H2[(size_t)MR * Dsz];

// ---------------------------------------------------------------------------
// Low-level helpers (base-ISA only: cp.async / ldmatrix / mma.sync)
// ---------------------------------------------------------------------------
__device__ __forceinline__ uint32_t smem_u32(const void* p) {
    uint32_t a;
    asm("{ .reg .u64 t; cvta.to.shared.u64 t, %1; cvt.u32.u64 %0, t; }" : "=r"(a) : "l"(p));
    return a;
}
template<int N> __device__ __forceinline__ void cp_wait() {
    asm volatile("cp.async.wait_group %0;" :: "n"(N));
}
__device__ __forceinline__ void cp16(uint32_t s, const void* g) {
    asm volatile("cp.async.cg.shared.global [%0], [%1], 16;" :: "r"(s), "l"(g));
}
__device__ __forceinline__ void cp_commit() { asm volatile("cp.async.commit_group;"); }
__device__ __forceinline__ void ldm4(uint32_t* d, uint32_t a) {
    asm volatile("ldmatrix.sync.aligned.m8n8.x4.shared.b16 {%0,%1,%2,%3}, [%4];"
                 : "=r"(d[0]), "=r"(d[1]), "=r"(d[2]), "=r"(d[3]) : "r"(a));
}
__device__ __forceinline__ void mma16816(float* c, const uint32_t* a, uint32_t b0, uint32_t b1) {
    asm volatile("mma.sync.aligned.m16n8k16.row.col.f32.bf16.bf16.f32 "
                 "{%0,%1,%2,%3}, {%4,%5,%6,%7}, {%8,%9}, {%0,%1,%2,%3};"
                 : "+f"(c[0]), "+f"(c[1]), "+f"(c[2]), "+f"(c[3])
                 : "r"(a[0]), "r"(a[1]), "r"(a[2]), "r"(a[3]), "r"(b0), "r"(b1));
}
__device__ __forceinline__ void sts16(uint32_t a, uint32_t x, uint32_t y, uint32_t z, uint32_t w) {
    asm volatile("st.shared.v4.b32 [%0], {%1,%2,%3,%4};" :: "r"(a), "r"(x), "r"(y), "r"(z), "r"(w));
}
__device__ __forceinline__ uint32_t swz(uint32_t o) { return o ^ ((o >> 3) & 0x70); }
__device__ __forceinline__ void split2(float v, bf16& h, bf16& l) {
    h = __float2bfloat16_rn(v);
    l = __float2bfloat16_rn(v - __bfloat162float(h));
}
__device__ __forceinline__ uint32_t bpack(bf16 a, bf16 b) {
    return (uint32_t)__bfloat16_as_ushort(a) | ((uint32_t)__bfloat16_as_ushort(b) << 16);
}

// ---------------------------------------------------------------------------
// fast exp (FMA pipe)
// ---------------------------------------------------------------------------
__device__ __forceinline__ float fast_exp(float x) {
    x = fmaxf(x, -87.0f);
    float t  = x * 1.4426950408889634f;
    float fi = floorf(t);
    float f  = t - fi;
    float p = 1.5252733e-5f;
    p = fmaf(p, f, 1.5403530e-4f);
    p = fmaf(p, f, 1.3333558e-3f);
    p = fmaf(p, f, 9.6181291e-3f);
    p = fmaf(p, f, 5.5504109e-2f);
    p = fmaf(p, f, 2.4022651e-1f);
    p = fmaf(p, f, 6.9314718e-1f);
    p = fmaf(p, f, 1.0f);
    return __int_as_float(__float_as_int(p) + ((int)fi << 23));
}

// ---------------------------------------------------------------------------
// Mask dtype detector
// ---------------------------------------------------------------------------
__global__ void detect_mask_kernel(const unsigned int* __restrict__ w) {
    __shared__ int flags[3];
    if (threadIdx.x < 3) flags[threadIdx.x] = 1;
    __syncthreads();
    int f32ok = 1, bf16ok = 1, i32ok = 1;
    for (int i = threadIdx.x; i < 1024; i += blockDim.x) {
        unsigned u = w[i];
        if (!(u == 0u || u == 0x3F800000u)) f32ok = 0;
        if (!(u == 0u || u == 0x3F800000u || u == 0x3F803F80u || u == 0x00003F80u)) bf16ok = 0;
        if (u > 1u) i32ok = 0;
    }
    if (!f32ok)  atomicAnd(&flags[0], 0);
    if (!bf16ok) atomicAnd(&flags[1], 0);
    if (!i32ok)  atomicAnd(&flags[2], 0);
    __syncthreads();
    if (threadIdx.x == 0)
        g_mask_mode = flags[0] ? 0 : (flags[1] ? 3 : (flags[2] ? 1 : 2));
}
__device__ __forceinline__ bool mask_true(const void* mask, long long off, int mode) {
    if (mode == 2) return ((const unsigned char*)mask)[off] != 0;
    if (mode == 1) return ((const int*)mask)[off] != 0;
    if (mode == 3) return ((const unsigned short*)mask)[off] != 0;
    return ((const float*)mask)[off] != 0.0f;
}

// ---------------------------------------------------------------------------
// fp32 -> hi/lo bf16 split (vectorized)
// ---------------------------------------------------------------------------
__global__ void split_kernel(const float* __restrict__ s, bf16* __restrict__ h,
                             bf16* __restrict__ l, long long n) {
    long long i = ((long long)blockIdx.x * blockDim.x + threadIdx.x) * 4;
    if (i >= n) return;
    float4 v = *(const float4*)(s + i);
    bf16 h0, l0, h1, l1, h2, l2, h3, l3;
    split2(v.x, h0, l0); split2(v.y, h1, l1);
    split2(v.z, h2, l2); split2(v.w, h3, l3);
    *(uint2*)(h + i) = make_uint2(bpack(h0, h1), bpack(h2, h3));
    *(uint2*)(l + i) = make_uint2(bpack(l0, l1), bpack(l2, l3));
}

// Pack wq|wk|wv ([H,D,64] each) into split planes [3072 rows, 1024 k]
__global__ void pack_w_split(const float* __restrict__ wq, const float* __restrict__ wk,
                             const float* __restrict__ wv) {
    long long i = (long long)blockIdx.x * blockDim.x + threadIdx.x;
    if (i >= (long long)Dsz * NQ) return;
    int d   = (int)(i % Dsz);
    int col = (int)(i / Dsz);
    int sel = col / 1024;
    int hr  = col % 1024;
    int h   = hr / 64, e = hr % 64;
    const float* w = (sel == 0) ? wq : (sel == 1) ? wk : wv;
    float v = w[((long long)h * Dsz + d) * 64 + e];
    bf16 hi, lo; split2(v, hi, lo);
    g_Wqkvh[i] = hi; g_Wqkvl[i] = lo;
}

// Transpose V planes: QKV cols [2048,3072) -> Vt [(b,h,e), s]
__global__ void vtrans_kernel() {
    __shared__ bf16 th[32][33], tl[32][33];
    int bh = blockIdx.z, b = bh >> 4, h = bh & 15;
    int s0 = blockIdx.x * 32, e0 = blockIdx.y * 32;
    int tx = threadIdx.x, ty = threadIdx.y;
    for (int i = ty; i < 32; i += 8) {
        long long src = ((long long)(b * 1024 + s0 + i)) * NQ + 2048 + h * 64 + e0 + tx;
        th[i][tx] = g_QKVh[src];
        tl[i][tx] = g_QKVl[src];
    }
    __syncthreads();
    for (int i = ty; i < 32; i += 8) {
        long long dst = ((long long)bh * 64 + e0 + i) * 1024 + s0 + tx;
        g_Vth[dst] = th[tx][i];
        g_Vtl[dst] = tl[tx][i];
    }
}

// ---------------------------------------------------------------------------
// Warp-MMA split-bf16 GEMM:  C = A @ B^T, 2-stage cp.async double buffer.
//   Per k-chunk: load 4 planes once, issue 3 MMA passes (hh, hl, lh).
//   EPI: 0 = write hi/lo planes; 1 = mask(-125)/scale -> fp16 (Cf is __half*);
//        2 = +bias fp32; 3 = +bias+relu -> hi/lo planes.
// ---------------------------------------------------------------------------
template<int BN, int EPI>
__global__ __launch_bounds__(256)
void mma_gemm(const bf16* __restrict__ Ah, const bf16* __restrict__ Al,
              int lda, long long sAb, long long sAh_,
              const bf16* __restrict__ Bh, const bf16* __restrict__ Bl,
              int ldb, long long sBb, long long sBh_,
              float* __restrict__ Cf, bf16* __restrict__ Ch, bf16* __restrict__ Cl,
              int ldc, long long sCb, long long sCh_,
              int K, const float* __restrict__ bias, const void* __restrict__ mask) {
    constexpr int BM  = 128;
    constexpr int WNw = BN / 4;
    constexpr int NT  = WNw / 8;
    constexpr int NLD = WNw / 16;
    constexpr int ATB = BM * 128;
    constexpr int BTB = BN * 128;
    constexpr int STG = 2 * ATB + 2 * BTB;

    extern __shared__ char smem[];
    const uint32_t sb = smem_u32(smem);

    const int tid = threadIdx.x, wid = tid >> 5, lane = tid & 31;
    const int wM = wid >> 2, wN = wid & 3;
    const int g = lane >> 3, r = lane & 7;

    const int bz = blockIdx.z, bb = bz >> 4, hz = bz & 15;
    const bf16* Ahb = Ah + bb * sAb + hz * sAh_ + (long long)blockIdx.y * BM * lda;
    const bf16* Alb = Al + bb * sAb + hz * sAh_ + (long long)blockIdx.y * BM * lda;
    const int n0 = blockIdx.x * BN;
    const bf16* Bhb = Bh + bb * sBb + hz * sBh_ + (long long)n0 * ldb;
    const bf16* Blb = Bl + bb * sBb + hz * sBh_ + (long long)n0 * ldb;

    const int KC = K >> 6;

    float acc[4][NT][4];
#pragma unroll
    for (int a = 0; a < 4; a++)
#pragma unroll
        for (int b = 0; b < NT; b++)
#pragma unroll
            for (int c = 0; c < 4; c++) acc[a][b][c] = 0.0f;

    auto issue = [&](int kc, int buf) {
        int k0 = kc << 6;
        uint32_t aH = sb + buf * STG;
        uint32_t aL = aH + ATB;
        uint32_t bH = aL + ATB;
        uint32_t bL = bH + BTB;
#pragma unroll
        for (int w = 0; w < 4; w++) {
            int idx = w * 256 + tid, row = idx >> 3, seg = idx & 7;
            uint32_t so = swz(row * 128 + seg * 16);
            long long go = (long long)row * lda + k0 + seg * 8;
            cp16(aH + so, Ahb + go);
            cp16(aL + so, Alb + go);
        }
#pragma unroll
        for (int w = 0; w < BN / 32; w++) {
            int idx = w * 256 + tid, row = idx >> 3, seg = idx & 7;
            uint32_t so = swz(row * 128 + seg * 16);
            long long go = (long long)row * ldb + k0 + seg * 8;
            cp16(bH + so, Bhb + go);
            cp16(bL + so, Blb + go);
        }
        cp_commit();
    };

    issue(0, 0);
    for (int kc = 0; kc < KC; kc++) {
        if (kc + 1 < KC) { issue(kc + 1, (kc + 1) & 1); cp_wait<1>(); }
        else             { cp_wait<0>(); }
        __syncthreads();
        const uint32_t aH = sb + (kc & 1) * STG;
        const uint32_t aL = aH + ATB;
        const uint32_t bH = aL + ATB;
        const uint32_t bL = bH + BTB;
#pragma unroll
        for (int ks = 0; ks < 4; ks++) {
            uint32_t ahf[4][4], alf[4][4];
#pragma unroll
            for (int mt = 0; mt < 4; mt++) {
                int rw = wM * 64 + mt * 16 + (g & 1) * 8 + r;
                uint32_t so = swz((uint32_t)(rw * 128 + ks * 32 + (g >> 1) * 16));
                ldm4(ahf[mt], aH + so);
                ldm4(alf[mt], aL + so);
            }
            uint32_t bhf[NLD][4], blf[NLD][4];
#pragma unroll
            for (int nl = 0; nl < NLD; nl++) {
                int rw = wN * WNw + nl * 16 + (g >> 1) * 8 + r;
                uint32_t so = swz((uint32_t)(rw * 128 + ks * 32 + (g & 1) * 16));
                ldm4(bhf[nl], bH + so);
                ldm4(blf[nl], bL + so);
            }
#pragma unroll
            for (int mt = 0; mt < 4; mt++)
#pragma unroll
                for (int j = 0; j < NT; j++)
                    mma16816(acc[mt][j], ahf[mt], bhf[j >> 1][(j & 1) * 2], bhf[j >> 1][(j & 1) * 2 + 1]);
#pragma unroll
            for (int mt = 0; mt < 4; mt++)
#pragma unroll
                for (int j = 0; j < NT; j++)
                    mma16816(acc[mt][j], ahf[mt], blf[j >> 1][(j & 1) * 2], blf[j >> 1][(j & 1) * 2 + 1]);
#pragma unroll
            for (int mt = 0; mt < 4; mt++)
#pragma unroll
                for (int j = 0; j < NT; j++)
                    mma16816(acc[mt][j], alf[mt], bhf[j >> 1][(j & 1) * 2], bhf[j >> 1][(j & 1) * 2 + 1]);
        }
        __syncthreads();
    }

    // ---- epilogue ----
    const int rb  = blockIdx.y * BM + wM * 64;
    const int cb0 = n0 + wN * WNw;
    float*  Cfb = (EPI == 2) ? (Cf + bb * sCb + hz * sCh_) : nullptr;
    __half* Chalf = (EPI == 1) ? ((__half*)Cf + bb * sCb + hz * sCh_) : nullptr;
    bf16*   Chb = (EPI == 0 || EPI == 3) ? (Ch + bb * sCb + hz * sCh_) : nullptr;
    bf16*   Clb = (EPI == 0 || EPI == 3) ? (Cl + bb * sCb + hz * sCh_) : nullptr;
    const int mmode = (EPI == 1) ? g_mask_mode : 0;

#pragma unroll
    for (int mt = 0; mt < 4; mt++)
#pragma unroll
        for (int j = 0; j < NT; j++) {
            int row0 = rb + mt * 16 + (lane >> 2);
            int col  = cb0 + j * 8 + (lane & 3) * 2;
#pragma unroll
            for (int h2 = 0; h2 < 2; h2++) {
                int row = row0 + h2 * 8;
                float v0 = acc[mt][j][h2 * 2 + 0];
                float v1 = acc[mt][j][h2 * 2 + 1];
                if (EPI == 2 || EPI == 3) { v0 += bias[col]; v1 += bias[col + 1]; }
                if (EPI == 3) { v0 = fmaxf(v0, 0.0f); v1 = fmaxf(v1, 0.0f); }
                if (EPI == 1) {
                    long long mb = (long long)bb * Ssz * Ssz + (long long)row * Ssz;
                    v0 = mask_true(mask, mb + col,     mmode) ? v0 * 0.125f : -125.0f;
                    v1 = mask_true(mask, mb + col + 1, mmode) ? v1 * 0.125f : -125.0f;
                }
                long long co = (long long)row * ldc + col;
                if (EPI == 1) {
                    *(__half2*)(Chalf + co) = __floats2half2_rn(v0, v1);
                } else if (EPI == 2) {
                    *(float2*)(Cfb + co) = make_float2(v0, v1);
                } else {
                    bf16 h0, l0, h1, l1;
                    split2(v0, h0, l0); split2(v1, h1, l1);
                    *(uint32_t*)(Chb + co) = bpack(h0, h1);
                    *(uint32_t*)(Clb + co) = bpack(l0, l1);
                }
            }
        }
}

// ---------------------------------------------------------------------------
// Column stats over the QUERY axis: M[k] = max_q s, CI[k] = 1/sum_q exp(s-M)
// ---------------------------------------------------------------------------
__global__ __launch_bounds__(256)
void col_stats_kernel(const __half* __restrict__ Sh, float* __restrict__ CM,
                      float* __restrict__ CI) {
    const int c = threadIdx.x & 63;
    const int r = threadIdx.x >> 6;
    const int bh = blockIdx.y;
    const int coff = blockIdx.x * 64 + c;
    const __half* base = Sh + (long long)bh * ((long long)Ssz * Ssz) + coff;

    float m = -3.0e38f, l = 0.0f;
    for (int q = r; q < Ssz; q += 4) {
        float v = __half2float(base[(long long)q * Ssz]);
        float mn = fmaxf(m, v);
        l = l * fast_exp(m - mn) + fast_exp(v - mn);
        m = mn;
    }
    __shared__ float sm[4][64], sl[4][64];
    sm[r][c] = m; sl[r][c] = l;
    __syncthreads();
    if (r == 0) {
        float M = m, L = l;
#pragma unroll
        for (int i = 1; i < 4; i++) {
            float m2 = sm[i][c], l2 = sl[i][c];
            float mn = fmaxf(M, m2);
            L = L * fast_exp(M - mn) + l2 * fast_exp(m2 - mn);
            M = mn;
        }
        CM[(long long)bh * Ssz + coff] = M;
        CI[(long long)bh * Ssz + coff] = 1.0f / L;
    }
}

// ---------------------------------------------------------------------------
// Fused softmax + P@Vt^T GEMM (G3). A = softmax(S) computed in the loader:
// p = exp(s - M[k]) * CI[k], split to hi/lo bf16 planes in smem.
// BM=128, BN=64, BK=64, KC=16. S register-prefetched; Vt via cp.async.
// ---------------------------------------------------------------------------
__global__ __launch_bounds__(256)
void pv_gemm(const __half* __restrict__ Sh, const float* __restrict__ CM,
             const float* __restrict__ CI,
             const bf16* __restrict__ Vth, const bf16* __restrict__ Vtl,
             bf16* __restrict__ Oh, bf16* __restrict__ Ol) {
    constexpr int BM = 128, BN = 64;
    constexpr int ATB = BM * 128;            // 16 KB per A plane
    constexpr int BTB = BN * 128;            // 8 KB per B plane
    constexpr int STG = 2 * ATB + 2 * BTB;   // 48 KB
    constexpr int KC = 16;

    extern __shared__ char smem[];
    const uint32_t sb = smem_u32(smem);
    const int tid = threadIdx.x, wid = tid >> 5, lane = tid & 31;
    const int wM = wid >> 2, wN = wid & 3;
    const int g = lane >> 3, r = lane & 7;

    const int bh = blockIdx.z;
    const __half* Sb = Sh + (long long)bh * ((long long)Ssz * Ssz)
                          + (long long)blockIdx.y * BM * Ssz;
    const float* CMb = CM + (long long)bh * Ssz;
    const float* CIb = CI + (long long)bh * Ssz;
    const bf16* Bhb = Vth + (long long)bh * 64 * Ssz;
    const bf16* Blb = Vtl + (long long)bh * 64 * Ssz;

    float acc[4][2][4];
#pragma unroll
    for (int a = 0; a < 4; a++)
#pragma unroll
        for (int b = 0; b < 2; b++)
#pragma unroll
            for (int c = 0; c < 4; c++) acc[a][b][c] = 0.0f;

    uint4 pre[2][4];

    auto ldgA = [&](int kc, uint4* dst) {
        int k0 = kc << 6;
#pragma unroll
        for (int it = 0; it < 4; it++) {
            int idx = it * 256 + tid, row = idx >> 3, seg = idx & 7;
            dst[it] = *(const uint4*)(Sb + (long long)row * Ssz + k0 + seg * 8);
        }
    };
    auto cpB = [&](int kc, int buf) {
        int k0 = kc << 6;
        uint32_t bH = sb + buf * STG + 2 * ATB, bL = bH + BTB;
#pragma unroll
        for (int w = 0; w < 2; w++) {
            int idx = w * 256 + tid, row = idx >> 3, seg = idx & 7;
            uint32_t so = swz(row * 128 + seg * 16);
            long long go = (long long)row * Ssz + k0 + seg * 8;
            cp16(bH + so, Bhb + go);
            cp16(bL + so, Blb + go);
        }
        cp_commit();
    };
    auto convert = [&](const uint4* src, int kc, int buf) {
        int k0 = kc << 6;
        uint32_t aH = sb + buf * STG, aL = aH + ATB;
#pragma unroll
        for (int it = 0; it < 4; it++) {
            int idx = it * 256 + tid, row = idx >> 3, seg = idx & 7;
            int kb = k0 + seg * 8;
            float4 m0 = __ldg((const float4*)(CMb + kb));
            float4 m1 = __ldg((const float4*)(CMb + kb + 4));
            float4 i0 = __ldg((const float4*)(CIb + kb));
            float4 i1 = __ldg((const float4*)(CIb + kb + 4));
            const __half* hp = (const __half*)&src[it];
            float p[8];
            p[0] = fast_exp(__half2float(hp[0]) - m0.x) * i0.x;
            p[1] = fast_exp(__half2float(hp[1]) - m0.y) * i0.y;
            p[2] = fast_exp(__half2float(hp[2]) - m0.z) * i0.z;
            p[3] = fast_exp(__half2float(hp[3]) - m0.w) * i0.w;
            p[4] = fast_exp(__half2float(hp[4]) - m1.x) * i1.x;
            p[5] = fast_exp(__half2float(hp[5]) - m1.y) * i1.y;
            p[6] = fast_exp(__half2float(hp[6]) - m1.z) * i1.z;
            p[7] = fast_exp(__half2float(hp[7]) - m1.w) * i1.w;
            bf16 H[8], L[8];
#pragma unroll
            for (int u = 0; u < 8; u++) split2(p[u], H[u], L[u]);
            uint32_t so = swz((uint32_t)(row * 128 + seg * 16));
            sts16(aH + so, bpack(H[0], H[1]), bpack(H[2], H[3]),
                           bpack(H[4], H[5]), bpack(H[6], H[7]));
            sts16(aL + so, bpack(L[0], L[1]), bpack(L[2], L[3]),
                           bpack(L[4], L[5]), bpack(L[6], L[7]));
        }
    };

    ldgA(0, pre[0]);
    cpB(0, 0);
    for (int kc = 0; kc < KC; kc++) {
        const int buf = kc & 1;
        if (kc + 1 < KC) { ldgA(kc + 1, pre[buf ^ 1]); cpB(kc + 1, buf ^ 1); cp_wait<1>(); }
        else             { cp_wait<0>(); }
        convert(pre[buf], kc, buf);
        __syncthreads();
        const uint32_t aH = sb + buf * STG;
        const uint32_t aL = aH + ATB;
        const uint32_t bH = aL + ATB;
        const uint32_t bL = bH + BTB;
#pragma unroll
        for (int ks = 0; ks < 4; ks++) {
            uint32_t ahf[4][4], alf[4][4];
#pragma unroll
            for (int mt = 0; mt < 4; mt++) {
                int rw = wM * 64 + mt * 16 + (g & 1) * 8 + r;
                uint32_t so = swz((uint32_t)(rw * 128 + ks * 32 + (g >> 1) * 16));
                ldm4(ahf[mt], aH + so);
                ldm4(alf[mt], aL + so);
            }
            uint32_t bhf[4], blf[4];
            {
                int rw = wN * 16 + (g >> 1) * 8 + r;
                uint32_t so = swz((uint32_t)(rw * 128 + ks * 32 + (g & 1) * 16));
                ldm4(bhf, bH + so);
                ldm4(blf, bL + so);
            }
#pragma unroll
            for (int mt = 0; mt < 4; mt++)
#pragma unroll
                for (int j = 0; j < 2; j++)
                    mma16816(acc[mt][j], ahf[mt], bhf[j * 2], bhf[j * 2 + 1]);
#pragma unroll
            for (int mt = 0; mt < 4; mt++)
#pragma unroll
                for (int j = 0; j < 2; j++)
                    mma16816(acc[mt][j], ahf[mt], blf[j * 2], blf[j * 2 + 1]);
#pragma unroll
            for (int mt = 0; mt < 4; mt++)
#pragma unroll
                for (int j = 0; j < 2; j++)
                    mma16816(acc[mt][j], alf[mt], bhf[j * 2], bhf[j * 2 + 1]);
        }
        __syncthreads();
    }

    // ---- epilogue: write O hi/lo planes at [b*1024+q, h*64+e] ----
    const int rowb = (bh >> 4) * 1024 + blockIdx.y * BM + wM * 64;
    const int colb = (bh & 15) * 64 + wN * 16;
#pragma unroll
    for (int mt = 0; mt < 4; mt++)
#pragma unroll
        for (int j = 0; j < 2; j++) {
            int row0 = rowb + mt * 16 + (lane >> 2);
            int col  = colb + j * 8 + (lane & 3) * 2;
#pragma unroll
            for (int h2 = 0; h2 < 2; h2++) {
                int row = row0 + h2 * 8;
                float v0 = acc[mt][j][h2 * 2 + 0];
                float v1 = acc[mt][j][h2 * 2 + 1];
                long long co = (long long)row * Dsz + col;
                bf16 h0, l0, h1, l1;
                split2(v0, h0, l0); split2(v1, h1, l1);
                *(uint32_t*)(g_Oh + co) = bpack(h0, h1);
                *(uint32_t*)(g_Ol + co) = bpack(l0, l1);
            }
        }
}

// ---------------------------------------------------------------------------
// Fused residual-add + LayerNorm; optional hi/lo plane emission
// ---------------------------------------------------------------------------
template<bool PL>
__global__ __launch_bounds__(256)
void ln_kernel(const float* __restrict__ a, const float* __restrict__ b,
               const float* __restrict__ g, const float* __restrict__ beta,
               float* __restrict__ out, bf16* __restrict__ oh, bf16* __restrict__ ol) {
    const int t = threadIdx.x;
    const long long base = (long long)blockIdx.x * Dsz;
    float v[4];
    float s = 0.0f;
#pragma unroll
    for (int j = 0; j < 4; j++) {
        int idx = t + j * 256;
        v[j] = a[base + idx] + b[base + idx];
        s += v[j];
    }
    __shared__ float red[8];
    __shared__ float bc, bc2;
#pragma unroll
    for (int o = 16; o; o >>= 1) s += __shfl_xor_sync(0xffffffffu, s, o);
    if ((t & 31) == 0) red[t >> 5] = s;
    __syncthreads();
    if (t == 0) {
        float tt = 0;
#pragma unroll
        for (int i = 0; i < 8; i++) tt += red[i];
        bc = tt * (1.0f / 1024.0f);
    }
    __syncthreads();
    const float mu = bc;
    float q = 0.0f;
#pragma unroll
    for (int j = 0; j < 4; j++) { float d = v[j] - mu; q += d * d; }
    __syncthreads();
#pragma unroll
    for (int o = 16; o; o >>= 1) q += __shfl_xor_sync(0xffffffffu, q, o);
    if ((t & 31) == 0) red[t >> 5] = q;
    __syncthreads();
    if (t == 0) {
        float tt = 0;
#pragma unroll
        for (int i = 0; i < 8; i++) tt += red[i];
        bc2 = rsqrtf(tt * (1.0f / 1024.0f) + 1e-5f);
    }
    __syncthreads();
    const float rs = bc2;
#pragma unroll
    for (int j = 0; j < 4; j++) {
        int idx = t + j * 256;
        float o = (v[j] - mu) * rs * g[idx] + beta[idx];
        out[base + idx] = o;
        if (PL) {
            bf16 h, l; split2(o, h, l);
            oh[base + idx] = h; ol[base + idx] = l;
        }
    }
}

// ---------------------------------------------------------------------------
// Launch
// ---------------------------------------------------------------------------
extern "C" void kernel_launch(void* const* d_in, const int* in_sizes, int n_in,
                              void* d_out, int out_size) {
    const float* x     = (const float*)d_in[0];
    const void*  mask  = d_in[1];
    const float* wq    = (const float*)d_in[2];
    const float* wk    = (const float*)d_in[3];
    const float* wv    = (const float*)d_in[4];
    const float* fc_w  = (const float*)d_in[5];
    const float* fc_b  = (const float*)d_in[6];
    const float* w1    = (const float*)d_in[7];
    const float* b1    = (const float*)d_in[8];
    const float* w2    = (const float*)d_in[9];
    const float* b2    = (const float*)d_in[10];
    const float* ln1_g = (const float*)d_in[11];
    const float* ln1_b = (const float*)d_in[12];
    const float* ln2_g = (const float*)d_in[13];
    const float* ln2_b = (const float*)d_in[14];
    float* out = (float*)d_out;

    bf16 *Xh, *Xl, *Wqh, *Wql, *FCh, *FCl, *W1h, *W1l, *W2h, *W2l;
    bf16 *QKVh, *QKVl, *Vth, *Vtl, *Oh, *Ol, *X1h, *X1l, *H1h, *H1l;
    __half* Sh;
    float *CM, *CI, *ATT, *X1, *H2;
    cudaGetSymbolAddress((void**)&Xh, g_Xh);     cudaGetSymbolAddress((void**)&Xl, g_Xl);
    cudaGetSymbolAddress((void**)&Wqh, g_Wqkvh); cudaGetSymbolAddress((void**)&Wql, g_Wqkvl);
    cudaGetSymbolAddress((void**)&FCh, g_FCh);   cudaGetSymbolAddress((void**)&FCl, g_FCl);
    cudaGetSymbolAddress((void**)&W1h, g_W1h);   cudaGetSymbolAddress((void**)&W1l, g_W1l);
    cudaGetSymbolAddress((void**)&W2h, g_W2h);   cudaGetSymbolAddress((void**)&W2l, g_W2l);
    cudaGetSymbolAddress((void**)&QKVh, g_QKVh); cudaGetSymbolAddress((void**)&QKVl, g_QKVl);
    cudaGetSymbolAddress((void**)&Vth, g_Vth);   cudaGetSymbolAddress((void**)&Vtl, g_Vtl);
    cudaGetSymbolAddress((void**)&Sh, g_Sh);
    cudaGetSymbolAddress((void**)&CM, g_CM);     cudaGetSymbolAddress((void**)&CI, g_CI);
    cudaGetSymbolAddress((void**)&Oh, g_Oh);     cudaGetSymbolAddress((void**)&Ol, g_Ol);
    cudaGetSymbolAddress((void**)&ATT, g_ATT);
    cudaGetSymbolAddress((void**)&X1, g_X1);
    cudaGetSymbolAddress((void**)&X1h, g_X1h);   cudaGetSymbolAddress((void**)&X1l, g_X1l);
    cudaGetSymbolAddress((void**)&H1h, g_H1h);   cudaGetSymbolAddress((void**)&H1l, g_H1l);
    cudaGetSymbolAddress((void**)&H2, g_H2);

    constexpr int SM128 = 2 * 2 * (128 + 128) * 128;   // 131072 (2 stages, proven)
    constexpr int PVSM  = 2 * (2 * 128 * 128 + 2 * 64 * 128);  // 98304
    cudaFuncSetAttribute(mma_gemm<128, 0>, cudaFuncAttributeMaxDynamicSharedMemorySize, SM128);
    cudaFuncSetAttribute(mma_gemm<128, 1>, cudaFuncAttributeMaxDynamicSharedMemorySize, SM128);
    cudaFuncSetAttribute(mma_gemm<128, 2>, cudaFuncAttributeMaxDynamicSharedMemorySize, SM128);
    cudaFuncSetAttribute(mma_gemm<128, 3>, cudaFuncAttributeMaxDynamicSharedMemorySize, SM128);
    cudaFuncSetAttribute(pv_gemm,          cudaFuncAttributeMaxDynamicSharedMemorySize, PVSM);

    detect_mask_kernel<<<1, 256>>>((const unsigned int*)mask);

    // Input / weight splits
    split_kernel<<<(MR * Dsz / 4 + 255) / 256, 256>>>(x, Xh, Xl, (long long)MR * Dsz);
    pack_w_split<<<((long long)Dsz * NQ + 255) / 256, 256>>>(wq, wk, wv);
    split_kernel<<<((long long)Dsz * Dsz / 4 + 255) / 256, 256>>>(fc_w, FCh, FCl, (long long)Dsz * Dsz);
    split_kernel<<<((long long)FFsz * Dsz / 4 + 255) / 256, 256>>>(w1, W1h, W1l, (long long)FFsz * Dsz);
    split_kernel<<<((long long)Dsz * FFsz / 4 + 255) / 256, 256>>>(w2, W2h, W2l, (long long)Dsz * FFsz);

    // G1: QKV planes = X @ Wqkv^T
    mma_gemm<128, 0><<<dim3(NQ / 128, MR / 128, 1), 256, SM128>>>(
        Xh, Xl, Dsz, 0, 0, Wqh, Wql, Dsz, 0, 0,
        nullptr, QKVh, QKVl, NQ, 0, 0, Dsz, nullptr, nullptr);

    // V transpose into Vt planes
    vtrans_kernel<<<dim3(32, 2, 128), dim3(32, 8)>>>();

    // G2: S(fp16) = mask/scale(Q @ K^T) per (b,h)
    mma_gemm<128, 1><<<dim3(Ssz / 128, Ssz / 128, Bsz * Hsz), 256, SM128>>>(
        QKVh, QKVl, NQ, (long long)Ssz * NQ, 64,
        QKVh + 1024, QKVl + 1024, NQ, (long long)Ssz * NQ, 64,
        (float*)Sh, nullptr, nullptr, Ssz, (long long)Hsz * Ssz * Ssz, (long long)Ssz * Ssz,
        DKsz, nullptr, mask);

    // Column softmax stats (max, 1/sum) over query axis
    col_stats_kernel<<<dim3(Ssz / 64, Bsz * Hsz), 256>>>(Sh, CM, CI);

    // G3 fused: O planes = softmax(S) @ Vt^T per (b,h)
    pv_gemm<<<dim3(1, Ssz / 128, Bsz * Hsz), 256, PVSM>>>(Sh, CM, CI, Vth, Vtl, Oh, Ol);

    // G4: ATT = O @ fc_w^T + fc_b (fp32)
    mma_gemm<128, 2><<<dim3(Dsz / 128, MR / 128, 1), 256, SM128>>>(
        Oh, Ol, Dsz, 0, 0, FCh, FCl, Dsz, 0, 0,
        ATT, nullptr, nullptr, Dsz, 0, 0, Dsz, fc_b, nullptr);

    // LN1 -> X1 fp32 + planes
    ln_kernel<true><<<MR, 256>>>(ATT, x, ln1_g, ln1_b, X1, X1h, X1l);

    // G5: H1 planes = relu(X1 @ w1^T + b1)
    mma_gemm<128, 3><<<dim3(FFsz / 128, MR / 128, 1), 256, SM128>>>(
        X1h, X1l, Dsz, 0, 0, W1h, W1l, Dsz, 0, 0,
        nullptr, H1h, H1l, FFsz, 0, 0, Dsz, b1, nullptr);

    // G6: H2 = H1 @ w2^T + b2 (fp32)
    mma_gemm<128, 2><<<dim3(Dsz / 128, MR / 128, 1), 256, SM128>>>(
        H1h, H1l, FFsz, 0, 0, W2h, W2l, FFsz, 0, 0,
        H2, nullptr, nullptr, Dsz, 0, 0, FFsz, b2, nullptr);

    // LN2 -> out
    ln_kernel<false><<<MR, 256>>>(H2, X1, ln2_g, ln2_b, out, nullptr, nullptr);
}

// round 14
// speedup vs baseline: 1.5320x; 1.5320x over previous
#include <cuda_runtime.h>
#include <cuda_bf16.h>
#include <cuda_fp16.h>
#include <math.h>
#include <stdint.h>

constexpr int Bsz = 8, Ssz = 1024, Dsz = 1024, Hsz = 16, DKsz = 64, FFsz = 4096;
constexpr int MR = Bsz * Ssz;          // 8192
constexpr int NQ = 3 * Hsz * DKsz;     // 3072

typedef __nv_bfloat16 bf16;

// ---------------------------------------------------------------------------
// Static device scratch (no allocations allowed)
// ---------------------------------------------------------------------------
__device__ int    g_mask_mode;
__device__ bf16   g_Xh[(size_t)MR * Dsz],      g_Xl[(size_t)MR * Dsz];
__device__ bf16   g_Wqkvh[(size_t)NQ * Dsz],   g_Wqkvl[(size_t)NQ * Dsz];
__device__ bf16   g_FCh[(size_t)Dsz * Dsz],    g_FCl[(size_t)Dsz * Dsz];
__device__ bf16   g_W1h[(size_t)FFsz * Dsz],   g_W1l[(size_t)FFsz * Dsz];
__device__ bf16   g_W2h[(size_t)Dsz * FFsz],   g_W2l[(size_t)Dsz * FFsz];
__device__ bf16   g_QKVh[(size_t)MR * NQ],     g_QKVl[(size_t)MR * NQ];
__device__ bf16   g_Vth[(size_t)Bsz * Hsz * DKsz * Ssz], g_Vtl[(size_t)Bsz * Hsz * DKsz * Ssz];
__device__ __half g_Sh[(size_t)Bsz * Hsz * Ssz * Ssz];       // fp16 masked/scaled logits
__device__ bf16   g_Ph[(size_t)Bsz * Hsz * Ssz * Ssz], g_Pl[(size_t)Bsz * Hsz * Ssz * Ssz];
__device__ bf16   g_Oh[(size_t)MR * Dsz],      g_Ol[(size_t)MR * Dsz];
__device__ float  g_ATT[(size_t)MR * Dsz];
__device__ float  g_X1[(size_t)MR * Dsz];
__device__ bf16   g_X1h[(size_t)MR * Dsz],     g_X1l[(size_t)MR * Dsz];
__device__ bf16   g_H1h[(size_t)MR * FFsz],    g_H1l[(size_t)MR * FFsz];
__device__ float  g_H2[(size_t)MR * Dsz];

// ---------------------------------------------------------------------------
// Low-level helpers (base-ISA only: cp.async / ldmatrix / mma.sync)
// ---------------------------------------------------------------------------
__device__ __forceinline__ uint32_t smem_u32(const void* p) {
    uint32_t a;
    asm("{ .reg .u64 t; cvta.to.shared.u64 t, %1; cvt.u32.u64 %0, t; }" : "=r"(a) : "l"(p));
    return a;
}
template<int N> __device__ __forceinline__ void cp_wait() {
    asm volatile("cp.async.wait_group %0;" :: "n"(N));
}
__device__ __forceinline__ void cp16(uint32_t s, const void* g) {
    asm volatile("cp.async.cg.shared.global [%0], [%1], 16;" :: "r"(s), "l"(g));
}
__device__ __forceinline__ void cp_commit() { asm volatile("cp.async.commit_group;"); }
__device__ __forceinline__ void ldm4(uint32_t* d, uint32_t a) {
    asm volatile("ldmatrix.sync.aligned.m8n8.x4.shared.b16 {%0,%1,%2,%3}, [%4];"
                 : "=r"(d[0]), "=r"(d[1]), "=r"(d[2]), "=r"(d[3]) : "r"(a));
}
__device__ __forceinline__ void mma16816(float* c, const uint32_t* a, uint32_t b0, uint32_t b1) {
    asm volatile("mma.sync.aligned.m16n8k16.row.col.f32.bf16.bf16.f32 "
                 "{%0,%1,%2,%3}, {%4,%5,%6,%7}, {%8,%9}, {%0,%1,%2,%3};"
                 : "+f"(c[0]), "+f"(c[1]), "+f"(c[2]), "+f"(c[3])
                 : "r"(a[0]), "r"(a[1]), "r"(a[2]), "r"(a[3]), "r"(b0), "r"(b1));
}
__device__ __forceinline__ uint32_t swz(uint32_t o) { return o ^ ((o >> 3) & 0x70); }
__device__ __forceinline__ void split2(float v, bf16& h, bf16& l) {
    h = __float2bfloat16_rn(v);
    l = __float2bfloat16_rn(v - __bfloat162float(h));
}
__device__ __forceinline__ uint32_t bpack(bf16 a, bf16 b) {
    return (uint32_t)__bfloat16_as_ushort(a) | ((uint32_t)__bfloat16_as_ushort(b) << 16);
}

// ---------------------------------------------------------------------------
// fast exp (FMA pipe)
// ---------------------------------------------------------------------------
__device__ __forceinline__ float fast_exp(float x) {
    x = fmaxf(x, -87.0f);
    float t  = x * 1.4426950408889634f;
    float fi = floorf(t);
    float f  = t - fi;
    float p = 1.5252733e-5f;
    p = fmaf(p, f, 1.5403530e-4f);
    p = fmaf(p, f, 1.3333558e-3f);
    p = fmaf(p, f, 9.6181291e-3f);
    p = fmaf(p, f, 5.5504109e-2f);
    p = fmaf(p, f, 2.4022651e-1f);
    p = fmaf(p, f, 6.9314718e-1f);
    p = fmaf(p, f, 1.0f);
    return __int_as_float(__float_as_int(p) + ((int)fi << 23));
}

// ---------------------------------------------------------------------------
// Mask dtype detector
// ---------------------------------------------------------------------------
__global__ void detect_mask_kernel(const unsigned int* __restrict__ w) {
    __shared__ int flags[3];
    if (threadIdx.x < 3) flags[threadIdx.x] = 1;
    __syncthreads();
    int f32ok = 1, bf16ok = 1, i32ok = 1;
    for (int i = threadIdx.x; i < 1024; i += blockDim.x) {
        unsigned u = w[i];
        if (!(u == 0u || u == 0x3F800000u)) f32ok = 0;
        if (!(u == 0u || u == 0x3F800000u || u == 0x3F803F80u || u == 0x00003F80u)) bf16ok = 0;
        if (u > 1u) i32ok = 0;
    }
    if (!f32ok)  atomicAnd(&flags[0], 0);
    if (!bf16ok) atomicAnd(&flags[1], 0);
    if (!i32ok)  atomicAnd(&flags[2], 0);
    __syncthreads();
    if (threadIdx.x == 0)
        g_mask_mode = flags[0] ? 0 : (flags[1] ? 3 : (flags[2] ? 1 : 2));
}
__device__ __forceinline__ bool mask_true(const void* mask, long long off, int mode) {
    if (mode == 2) return ((const unsigned char*)mask)[off] != 0;
    if (mode == 1) return ((const int*)mask)[off] != 0;
    if (mode == 3) return ((const unsigned short*)mask)[off] != 0;
    return ((const float*)mask)[off] != 0.0f;
}

// ---------------------------------------------------------------------------
// fp32 -> hi/lo bf16 split (vectorized)
// ---------------------------------------------------------------------------
__global__ void split_kernel(const float* __restrict__ s, bf16* __restrict__ h,
                             bf16* __restrict__ l, long long n) {
    long long i = ((long long)blockIdx.x * blockDim.x + threadIdx.x) * 4;
    if (i >= n) return;
    float4 v = *(const float4*)(s + i);
    bf16 h0, l0, h1, l1, h2, l2, h3, l3;
    split2(v.x, h0, l0); split2(v.y, h1, l1);
    split2(v.z, h2, l2); split2(v.w, h3, l3);
    *(uint2*)(h + i) = make_uint2(bpack(h0, h1), bpack(h2, h3));
    *(uint2*)(l + i) = make_uint2(bpack(l0, l1), bpack(l2, l3));
}

// Pack wq|wk|wv ([H,D,64] each) into split planes [3072 rows, 1024 k]
__global__ void pack_w_split(const float* __restrict__ wq, const float* __restrict__ wk,
                             const float* __restrict__ wv) {
    long long i = (long long)blockIdx.x * blockDim.x + threadIdx.x;
    if (i >= (long long)Dsz * NQ) return;
    int d   = (int)(i % Dsz);
    int col = (int)(i / Dsz);
    int sel = col / 1024;
    int hr  = col % 1024;
    int h   = hr / 64, e = hr % 64;
    const float* w = (sel == 0) ? wq : (sel == 1) ? wk : wv;
    float v = w[((long long)h * Dsz + d) * 64 + e];
    bf16 hi, lo; split2(v, hi, lo);
    g_Wqkvh[i] = hi; g_Wqkvl[i] = lo;
}

// Transpose V planes: QKV cols [2048,3072) -> Vt [(b,h,e), s]
__global__ void vtrans_kernel() {
    __shared__ bf16 th[32][33], tl[32][33];
    int bh = blockIdx.z, b = bh >> 4, h = bh & 15;
    int s0 = blockIdx.x * 32, e0 = blockIdx.y * 32;
    int tx = threadIdx.x, ty = threadIdx.y;
    for (int i = ty; i < 32; i += 8) {
        long long src = ((long long)(b * 1024 + s0 + i)) * NQ + 2048 + h * 64 + e0 + tx;
        th[i][tx] = g_QKVh[src];
        tl[i][tx] = g_QKVl[src];
    }
    __syncthreads();
    for (int i = ty; i < 32; i += 8) {
        long long dst = ((long long)bh * 64 + e0 + i) * 1024 + s0 + tx;
        g_Vth[dst] = th[tx][i];
        g_Vtl[dst] = tl[tx][i];
    }
}

// ---------------------------------------------------------------------------
// Warp-MMA split-bf16 GEMM:  C = A @ B^T, 2-stage cp.async double buffer.
//   Per k-chunk: load 4 planes once, issue 3 MMA passes (hh, hl, lh).
//   EPI: 0 = write hi/lo planes; 1 = mask(-125)/scale -> fp16 (Cf is __half*);
//        2 = +bias fp32; 3 = +bias+relu -> hi/lo planes.
// ---------------------------------------------------------------------------
template<int BN, int EPI>
__global__ __launch_bounds__(256)
void mma_gemm(const bf16* __restrict__ Ah, const bf16* __restrict__ Al,
              int lda, long long sAb, long long sAh_,
              const bf16* __restrict__ Bh, const bf16* __restrict__ Bl,
              int ldb, long long sBb, long long sBh_,
              float* __restrict__ Cf, bf16* __restrict__ Ch, bf16* __restrict__ Cl,
              int ldc, long long sCb, long long sCh_,
              int K, const float* __restrict__ bias, const void* __restrict__ mask) {
    constexpr int BM  = 128;
    constexpr int WNw = BN / 4;
    constexpr int NT  = WNw / 8;
    constexpr int NLD = WNw / 16;
    constexpr int ATB = BM * 128;
    constexpr int BTB = BN * 128;
    constexpr int STG = 2 * ATB + 2 * BTB;

    extern __shared__ char smem[];
    const uint32_t sb = smem_u32(smem);

    const int tid = threadIdx.x, wid = tid >> 5, lane = tid & 31;
    const int wM = wid >> 2, wN = wid & 3;
    const int g = lane >> 3, r = lane & 7;

    const int bz = blockIdx.z, bb = bz >> 4, hz = bz & 15;
    const bf16* Ahb = Ah + bb * sAb + hz * sAh_ + (long long)blockIdx.y * BM * lda;
    const bf16* Alb = Al + bb * sAb + hz * sAh_ + (long long)blockIdx.y * BM * lda;
    const int n0 = blockIdx.x * BN;
    const bf16* Bhb = Bh + bb * sBb + hz * sBh_ + (long long)n0 * ldb;
    const bf16* Blb = Bl + bb * sBb + hz * sBh_ + (long long)n0 * ldb;

    const int KC = K >> 6;

    float acc[4][NT][4];
#pragma unroll
    for (int a = 0; a < 4; a++)
#pragma unroll
        for (int b = 0; b < NT; b++)
#pragma unroll
            for (int c = 0; c < 4; c++) acc[a][b][c] = 0.0f;

    auto issue = [&](int kc, int buf) {
        int k0 = kc << 6;
        uint32_t aH = sb + buf * STG;
        uint32_t aL = aH + ATB;
        uint32_t bH = aL + ATB;
        uint32_t bL = bH + BTB;
#pragma unroll
        for (int w = 0; w < 4; w++) {
            int idx = w * 256 + tid, row = idx >> 3, seg = idx & 7;
            uint32_t so = swz(row * 128 + seg * 16);
            long long go = (long long)row * lda + k0 + seg * 8;
            cp16(aH + so, Ahb + go);
            cp16(aL + so, Alb + go);
        }
#pragma unroll
        for (int w = 0; w < BN / 32; w++) {
            int idx = w * 256 + tid, row = idx >> 3, seg = idx & 7;
            uint32_t so = swz(row * 128 + seg * 16);
            long long go = (long long)row * ldb + k0 + seg * 8;
            cp16(bH + so, Bhb + go);
            cp16(bL + so, Blb + go);
        }
        cp_commit();
    };

    issue(0, 0);
    for (int kc = 0; kc < KC; kc++) {
        if (kc + 1 < KC) { issue(kc + 1, (kc + 1) & 1); cp_wait<1>(); }
        else             { cp_wait<0>(); }
        __syncthreads();
        const uint32_t aH = sb + (kc & 1) * STG;
        const uint32_t aL = aH + ATB;
        const uint32_t bH = aL + ATB;
        const uint32_t bL = bH + BTB;
#pragma unroll
        for (int ks = 0; ks < 4; ks++) {
            uint32_t ahf[4][4], alf[4][4];
#pragma unroll
            for (int mt = 0; mt < 4; mt++) {
                int rw = wM * 64 + mt * 16 + (g & 1) * 8 + r;
                uint32_t so = swz((uint32_t)(rw * 128 + ks * 32 + (g >> 1) * 16));
                ldm4(ahf[mt], aH + so);
                ldm4(alf[mt], aL + so);
            }
            uint32_t bhf[NLD][4], blf[NLD][4];
#pragma unroll
            for (int nl = 0; nl < NLD; nl++) {
                int rw = wN * WNw + nl * 16 + (g >> 1) * 8 + r;
                uint32_t so = swz((uint32_t)(rw * 128 + ks * 32 + (g & 1) * 16));
                ldm4(bhf[nl], bH + so);
                ldm4(blf[nl], bL + so);
            }
#pragma unroll
            for (int mt = 0; mt < 4; mt++)
#pragma unroll
                for (int j = 0; j < NT; j++)
                    mma16816(acc[mt][j], ahf[mt], bhf[j >> 1][(j & 1) * 2], bhf[j >> 1][(j & 1) * 2 + 1]);
#pragma unroll
            for (int mt = 0; mt < 4; mt++)
#pragma unroll
                for (int j = 0; j < NT; j++)
                    mma16816(acc[mt][j], ahf[mt], blf[j >> 1][(j & 1) * 2], blf[j >> 1][(j & 1) * 2 + 1]);
#pragma unroll
            for (int mt = 0; mt < 4; mt++)
#pragma unroll
                for (int j = 0; j < NT; j++)
                    mma16816(acc[mt][j], alf[mt], bhf[j >> 1][(j & 1) * 2], bhf[j >> 1][(j & 1) * 2 + 1]);
        }
        __syncthreads();
    }

    // ---- epilogue ----
    const int rb  = blockIdx.y * BM + wM * 64;
    const int cb0 = n0 + wN * WNw;
    float*  Cfb = (EPI == 2) ? (Cf + bb * sCb + hz * sCh_) : nullptr;
    __half* Chalf = (EPI == 1) ? ((__half*)Cf + bb * sCb + hz * sCh_) : nullptr;
    bf16*   Chb = (EPI == 0 || EPI == 3) ? (Ch + bb * sCb + hz * sCh_) : nullptr;
    bf16*   Clb = (EPI == 0 || EPI == 3) ? (Cl + bb * sCb + hz * sCh_) : nullptr;
    const int mmode = (EPI == 1) ? g_mask_mode : 0;

#pragma unroll
    for (int mt = 0; mt < 4; mt++)
#pragma unroll
        for (int j = 0; j < NT; j++) {
            int row0 = rb + mt * 16 + (lane >> 2);
            int col  = cb0 + j * 8 + (lane & 3) * 2;
#pragma unroll
            for (int h2 = 0; h2 < 2; h2++) {
                int row = row0 + h2 * 8;
                float v0 = acc[mt][j][h2 * 2 + 0];
                float v1 = acc[mt][j][h2 * 2 + 1];
                if (EPI == 2 || EPI == 3) { v0 += bias[col]; v1 += bias[col + 1]; }
                if (EPI == 3) { v0 = fmaxf(v0, 0.0f); v1 = fmaxf(v1, 0.0f); }
                if (EPI == 1) {
                    long long mb = (long long)bb * Ssz * Ssz + (long long)row * Ssz;
                    v0 = mask_true(mask, mb + col,     mmode) ? v0 * 0.125f : -125.0f;
                    v1 = mask_true(mask, mb + col + 1, mmode) ? v1 * 0.125f : -125.0f;
                }
                long long co = (long long)row * ldc + col;
                if (EPI == 1) {
                    *(__half2*)(Chalf + co) = __floats2half2_rn(v0, v1);
                } else if (EPI == 2) {
                    *(float2*)(Cfb + co) = make_float2(v0, v1);
                } else {
                    bf16 h0, l0, h1, l1;
                    split2(v0, h0, l0); split2(v1, h1, l1);
                    *(uint32_t*)(Chb + co) = bpack(h0, h1);
                    *(uint32_t*)(Clb + co) = bpack(l0, l1);
                }
            }
        }
}

// ---------------------------------------------------------------------------
// Column softmax over the QUERY axis; reads fp16 S, writes hi/lo P planes
// ---------------------------------------------------------------------------
__global__ __launch_bounds__(256)
void col_softmax_kernel(const __half* __restrict__ S, bf16* __restrict__ Ph,
                        bf16* __restrict__ Pl) {
    const int c = threadIdx.x & 63;
    const int r = threadIdx.x >> 6;
    const long long zoff = (long long)blockIdx.y * ((long long)Ssz * Ssz);
    const int coff = blockIdx.x * 64 + c;
    const __half* base = S + zoff + coff;

    float m = -3.0e38f, l = 0.0f;
    for (int q = r; q < Ssz; q += 4) {
        float v = __half2float(base[(long long)q * Ssz]);
        float mn = fmaxf(m, v);
        l = l * fast_exp(m - mn) + fast_exp(v - mn);
        m = mn;
    }
    __shared__ float sm[4][64], sl[4][64];
    sm[r][c] = m; sl[r][c] = l;
    __syncthreads();
    if (r == 0) {
        float M = m, L = l;
#pragma unroll
        for (int i = 1; i < 4; i++) {
            float m2 = sm[i][c], l2 = sl[i][c];
            float mn = fmaxf(M, m2);
            L = L * fast_exp(M - mn) + l2 * fast_exp(m2 - mn);
            M = mn;
        }
        sm[0][c] = M;
        sl[0][c] = 1.0f / L;
    }
    __syncthreads();
    const float M = sm[0][c];
    const float inv = sl[0][c];
    for (int q = r; q < Ssz; q += 4) {
        long long off = zoff + (long long)q * Ssz + coff;
        float p = fast_exp(__half2float(base[(long long)q * Ssz]) - M) * inv;
        bf16 ph, pl; split2(p, ph, pl);
        Ph[off] = ph; Pl[off] = pl;
    }
}

// ---------------------------------------------------------------------------
// Fused residual-add + LayerNorm; optional hi/lo plane emission
// ---------------------------------------------------------------------------
template<bool PL>
__global__ __launch_bounds__(256)
void ln_kernel(const float* __restrict__ a, const float* __restrict__ b,
               const float* __restrict__ g, const float* __restrict__ beta,
               float* __restrict__ out, bf16* __restrict__ oh, bf16* __restrict__ ol) {
    const int t = threadIdx.x;
    const long long base = (long long)blockIdx.x * Dsz;
    float v[4];
    float s = 0.0f;
#pragma unroll
    for (int j = 0; j < 4; j++) {
        int idx = t + j * 256;
        v[j] = a[base + idx] + b[base + idx];
        s += v[j];
    }
    __shared__ float red[8];
    __shared__ float bc, bc2;
#pragma unroll
    for (int o = 16; o; o >>= 1) s += __shfl_xor_sync(0xffffffffu, s, o);
    if ((t & 31) == 0) red[t >> 5] = s;
    __syncthreads();
    if (t == 0) {
        float tt = 0;
#pragma unroll
        for (int i = 0; i < 8; i++) tt += red[i];
        bc = tt * (1.0f / 1024.0f);
    }
    __syncthreads();
    const float mu = bc;
    float q = 0.0f;
#pragma unroll
    for (int j = 0; j < 4; j++) { float d = v[j] - mu; q += d * d; }
    __syncthreads();
#pragma unroll
    for (int o = 16; o; o >>= 1) q += __shfl_xor_sync(0xffffffffu, q, o);
    if ((t & 31) == 0) red[t >> 5] = q;
    __syncthreads();
    if (t == 0) {
        float tt = 0;
#pragma unroll
        for (int i = 0; i < 8; i++) tt += red[i];
        bc2 = rsqrtf(tt * (1.0f / 1024.0f) + 1e-5f);
    }
    __syncthreads();
    const float rs = bc2;
#pragma unroll
    for (int j = 0; j < 4; j++) {
        int idx = t + j * 256;
        float o = (v[j] - mu) * rs * g[idx] + beta[idx];
        out[base + idx] = o;
        if (PL) {
            bf16 h, l; split2(o, h, l);
            oh[base + idx] = h; ol[base + idx] = l;
        }
    }
}

// ---------------------------------------------------------------------------
// Launch
// ---------------------------------------------------------------------------
extern "C" void kernel_launch(void* const* d_in, const int* in_sizes, int n_in,
                              void* d_out, int out_size) {
    const float* x     = (const float*)d_in[0];
    const void*  mask  = d_in[1];
    const float* wq    = (const float*)d_in[2];
    const float* wk    = (const float*)d_in[3];
    const float* wv    = (const float*)d_in[4];
    const float* fc_w  = (const float*)d_in[5];
    const float* fc_b  = (const float*)d_in[6];
    const float* w1    = (const float*)d_in[7];
    const float* b1    = (const float*)d_in[8];
    const float* w2    = (const float*)d_in[9];
    const float* b2    = (const float*)d_in[10];
    const float* ln1_g = (const float*)d_in[11];
    const float* ln1_b = (const float*)d_in[12];
    const float* ln2_g = (const float*)d_in[13];
    const float* ln2_b = (const float*)d_in[14];
    float* out = (float*)d_out;

    bf16 *Xh, *Xl, *Wqh, *Wql, *FCh, *FCl, *W1h, *W1l, *W2h, *W2l;
    bf16 *QKVh, *QKVl, *Vth, *Vtl, *Ph, *Pl, *Oh, *Ol, *X1h, *X1l, *H1h, *H1l;
    __half* Sh;
    float *ATT, *X1, *H2;
    cudaGetSymbolAddress((void**)&Xh, g_Xh);     cudaGetSymbolAddress((void**)&Xl, g_Xl);
    cudaGetSymbolAddress((void**)&Wqh, g_Wqkvh); cudaGetSymbolAddress((void**)&Wql, g_Wqkvl);
    cudaGetSymbolAddress((void**)&FCh, g_FCh);   cudaGetSymbolAddress((void**)&FCl, g_FCl);
    cudaGetSymbolAddress((void**)&W1h, g_W1h);   cudaGetSymbolAddress((void**)&W1l, g_W1l);
    cudaGetSymbolAddress((void**)&W2h, g_W2h);   cudaGetSymbolAddress((void**)&W2l, g_W2l);
    cudaGetSymbolAddress((void**)&QKVh, g_QKVh); cudaGetSymbolAddress((void**)&QKVl, g_QKVl);
    cudaGetSymbolAddress((void**)&Vth, g_Vth);   cudaGetSymbolAddress((void**)&Vtl, g_Vtl);
    cudaGetSymbolAddress((void**)&Sh, g_Sh);
    cudaGetSymbolAddress((void**)&Ph, g_Ph);     cudaGetSymbolAddress((void**)&Pl, g_Pl);
    cudaGetSymbolAddress((void**)&Oh, g_Oh);     cudaGetSymbolAddress((void**)&Ol, g_Ol);
    cudaGetSymbolAddress((void**)&ATT, g_ATT);
    cudaGetSymbolAddress((void**)&X1, g_X1);
    cudaGetSymbolAddress((void**)&X1h, g_X1h);   cudaGetSymbolAddress((void**)&X1l, g_X1l);
    cudaGetSymbolAddress((void**)&H1h, g_H1h);   cudaGetSymbolAddress((void**)&H1l, g_H1l);
    cudaGetSymbolAddress((void**)&H2, g_H2);

    constexpr int SM128 = 2 * 2 * (128 + 128) * 128;   // 131072 (2 stages, proven)
    constexpr int SM64  = 2 * 2 * (128 + 64) * 128;    //  98304
    cudaFuncSetAttribute(mma_gemm<128, 0>, cudaFuncAttributeMaxDynamicSharedMemorySize, SM128);
    cudaFuncSetAttribute(mma_gemm<128, 1>, cudaFuncAttributeMaxDynamicSharedMemorySize, SM128);
    cudaFuncSetAttribute(mma_gemm<128, 2>, cudaFuncAttributeMaxDynamicSharedMemorySize, SM128);
    cudaFuncSetAttribute(mma_gemm<128, 3>, cudaFuncAttributeMaxDynamicSharedMemorySize, SM128);
    cudaFuncSetAttribute(mma_gemm<64, 0>,  cudaFuncAttributeMaxDynamicSharedMemorySize, SM64);

    detect_mask_kernel<<<1, 256>>>((const unsigned int*)mask);

    // Input / weight splits
    split_kernel<<<(MR * Dsz / 4 + 255) / 256, 256>>>(x, Xh, Xl, (long long)MR * Dsz);
    pack_w_split<<<((long long)Dsz * NQ + 255) / 256, 256>>>(wq, wk, wv);
    split_kernel<<<((long long)Dsz * Dsz / 4 + 255) / 256, 256>>>(fc_w, FCh, FCl, (long long)Dsz * Dsz);
    split_kernel<<<((long long)FFsz * Dsz / 4 + 255) / 256, 256>>>(w1, W1h, W1l, (long long)FFsz * Dsz);
    split_kernel<<<((long long)Dsz * FFsz / 4 + 255) / 256, 256>>>(w2, W2h, W2l, (long long)Dsz * FFsz);

    // G1: QKV planes = X @ Wqkv^T
    mma_gemm<128, 0><<<dim3(NQ / 128, MR / 128, 1), 256, SM128>>>(
        Xh, Xl, Dsz, 0, 0, Wqh, Wql, Dsz, 0, 0,
        nullptr, QKVh, QKVl, NQ, 0, 0, Dsz, nullptr, nullptr);

    // V transpose into Vt planes
    vtrans_kernel<<<dim3(32, 2, 128), dim3(32, 8)>>>();

    // G2: S(fp16) = mask/scale(Q @ K^T) per (b,h)
    mma_gemm<128, 1><<<dim3(Ssz / 128, Ssz / 128, Bsz * Hsz), 256, SM128>>>(
        QKVh, QKVl, NQ, (long long)Ssz * NQ, 64,
        QKVh + 1024, QKVl + 1024, NQ, (long long)Ssz * NQ, 64,
        (float*)Sh, nullptr, nullptr, Ssz, (long long)Hsz * Ssz * Ssz, (long long)Ssz * Ssz,
        DKsz, nullptr, mask);

    // Column softmax (query axis) -> P planes
    col_softmax_kernel<<<dim3(Ssz / 64, Bsz * Hsz), 256>>>(Sh, Ph, Pl);

    // G3: O planes = P @ Vt^T per (b,h)
    mma_gemm<64, 0><<<dim3(1, Ssz / 128, Bsz * Hsz), 256, SM64>>>(
        Ph, Pl, Ssz, (long long)Hsz * Ssz * Ssz, (long long)Ssz * Ssz,
        Vth, Vtl, Ssz, (long long)Hsz * DKsz * Ssz, (long long)DKsz * Ssz,
        nullptr, Oh, Ol, Dsz, (long long)Ssz * Dsz, 64,
        Ssz, nullptr, nullptr);

    // G4: ATT = O @ fc_w^T + fc_b (fp32)
    mma_gemm<128, 2><<<dim3(Dsz / 128, MR / 128, 1), 256, SM128>>>(
        Oh, Ol, Dsz, 0, 0, FCh, FCl, Dsz, 0, 0,
        ATT, nullptr, nullptr, Dsz, 0, 0, Dsz, fc_b, nullptr);

    // LN1 -> X1 fp32 + planes
    ln_kernel<true><<<MR, 256>>>(ATT, x, ln1_g, ln1_b, X1, X1h, X1l);

    // G5: H1 planes = relu(X1 @ w1^T + b1)
    mma_gemm<128, 3><<<dim3(FFsz / 128, MR / 128, 1), 256, SM128>>>(
        X1h, X1l, Dsz, 0, 0, W1h, W1l, Dsz, 0, 0,
        nullptr, H1h, H1l, FFsz, 0, 0, Dsz, b1, nullptr);

    // G6: H2 = H1 @ w2^T + b2 (fp32)
    mma_gemm<128, 2><<<dim3(Dsz / 128, MR / 128, 1), 256, SM128>>>(
        H1h, H1l, FFsz, 0, 0, W2h, W2l, FFsz, 0, 0,
        H2, nullptr, nullptr, Dsz, 0, 0, FFsz, b2, nullptr);

    // LN2 -> out
    ln_kernel<false><<<MR, 256>>>(H2, X1, ln2_g, ln2_b, out, nullptr, nullptr);
}